// round 17
// baseline (speedup 1.0000x reference)
#include <cuda_runtime.h>
#include <cuda_fp16.h>
#include <stdint.h>
#include <math.h>

#define NB  8192
#define HID 2048
#define CD  256
#define KC  4096

// ---------------- static scratch (allocation-free), all fp16 ----------------
__device__ __align__(128) __half g_h16[(size_t)NB * HID];
__device__ __align__(128) __half g_v16[(size_t)NB * HID];
__device__ __align__(128) __half g_Wmu16[(size_t)HID * HID];
__device__ __align__(128) __half g_Win16[(size_t)CD * KC];
__device__ __align__(128) __half g_Wout16[(size_t)3 * HID * CD];
__device__ __align__(128) __half g_c16[(size_t)NB * CD];

// ---------------- helpers ----------------
__device__ __forceinline__ uint32_t smem_u32(const void* p) {
    uint32_t a;
    asm("{ .reg .u64 t; cvta.to.shared.u64 t, %1; cvt.u32.u64 %0, t; }" : "=r"(a) : "l"(p));
    return a;
}
__device__ __forceinline__ float sigm(float x) { return 1.0f / (1.0f + expf(-x)); }

#define CPA16(s, g) asm volatile("cp.async.cg.shared.global [%0], [%1], 16;" :: "r"(s), "l"(g))
#define CPC()       asm volatile("cp.async.commit_group;")
#define CPW(n)      asm volatile("cp.async.wait_group %0;" :: "n"(n))

__device__ __forceinline__ void ldsm4(uint32_t* d, uint32_t a) {
    asm volatile("ldmatrix.sync.aligned.m8n8.x4.shared.b16 {%0,%1,%2,%3}, [%4];"
                 : "=r"(d[0]), "=r"(d[1]), "=r"(d[2]), "=r"(d[3]) : "r"(a));
}
__device__ __forceinline__ void mma_f16(float* c, const uint32_t* a, uint32_t b0, uint32_t b1) {
    asm volatile("mma.sync.aligned.m16n8k16.row.col.f32.f16.f16.f32 "
                 "{%0,%1,%2,%3},{%4,%5,%6,%7},{%8,%9},{%0,%1,%2,%3};"
                 : "+f"(c[0]), "+f"(c[1]), "+f"(c[2]), "+f"(c[3])
                 : "r"(a[0]), "r"(a[1]), "r"(a[2]), "r"(a[3]), "r"(b0), "r"(b1));
}

// ---------------- single fused fp32 -> fp16 conversion (grid-stride) --------
__device__ __forceinline__ void conv4(const float* s, __half* d, int i)
{
    float4 x = *(const float4*)(s + i);
    __half2* D = (__half2*)(d + i);
    D[0] = __floats2half2_rn(x.x, x.y);
    D[1] = __floats2half2_rn(x.z, x.w);
}
__global__ __launch_bounds__(256) void k_conv_all(
    const float* __restrict__ h, const float* __restrict__ v,
    const float* __restrict__ Wmu, const float* __restrict__ Win,
    const float* __restrict__ Wout)
{
    const int QH = NB * HID / 4, QW = HID * HID / 4;
    const int QI = CD * KC / 4, QO = 3 * HID * CD / 4;
    const int QT = 2 * QH + QW + QI + QO;
    const int stride = gridDim.x * 256;
    for (int q = blockIdx.x * 256 + threadIdx.x; q < QT; q += stride) {
        int r = q;
        if (r < QH) { conv4(h, g_h16, r * 4); continue; }
        r -= QH;
        if (r < QH) { conv4(v, g_v16, r * 4); continue; }
        r -= QH;
        if (r < QW) { conv4(Wmu, g_Wmu16, r * 4); continue; }
        r -= QW;
        if (r < QI) { conv4(Win, g_Win16, r * 4); continue; }
        r -= QI;
        conv4(Wout, g_Wout16, r * 4);
    }
}

// =============================================================================
// k1/k2: block 128x128, 8 warps 2(M)x4(N), warp tile 64x32, 4-stage pipeline,
// one sync per stage — the PROVEN R10 configuration (2 CTAs/SM, 106 regs).
// k3: same mainloop + SMEM-STAGED COALESCED epilogue (new).
// =============================================================================

#define COMPUTE_SP_128x128(As, Bs)                                             \
    _Pragma("unroll")                                                          \
    for (int kk = 0; kk < 32; kk += 16) {                                      \
        uint32_t ah[4][4];                                                     \
        uint32_t aoff = (As) + wm * 5120 + (lane & 15) * 80 + (lane >> 4) * 16 + kk * 2; \
        _Pragma("unroll")                                                      \
        for (int mt = 0; mt < 4; mt++) ldsm4(ah[mt], aoff + mt * 1280);        \
        uint32_t boff = (Bs) + wn * 2560 + ((lane & 7) + ((lane >> 3) & 1) * 8) * 80 \
                        + (lane >> 4) * 16 + kk * 2;                           \
        _Pragma("unroll")                                                      \
        for (int np = 0; np < 2; np++) {                                       \
            uint32_t bh[4];                                                    \
            ldsm4(bh, boff + np * 1280);                                       \
            _Pragma("unroll")                                                  \
            for (int mt = 0; mt < 4; mt++) {                                   \
                mma_f16(c[mt][np*2],   ah[mt], bh[0], bh[2]);                  \
                mma_f16(c[mt][np*2+1], ah[mt], bh[1], bh[3]);                  \
            }                                                                  \
        }                                                                      \
    }

// ---------------- k1: ctrl = silu([h|v] @ W_in^T + b_in) --------------------
__global__ __launch_bounds__(256, 2) void k1_mma(const float* __restrict__ b_in)
{
    extern __shared__ char smem[];
    const int t = threadIdx.x, lane = t & 31, wid = t >> 5;
    const int wm = wid >> 2, wn = wid & 3;
    const int m0 = blockIdx.y * 128, n0 = blockIdx.x * 128;
    uint32_t sb = smem_u32(smem);
    float c[4][4][4] = {};

    auto load_stage = [&](int i, int buf) {
        int k0 = i * 32;
        const __half* ah; int kc;
        if (k0 < HID) { ah = g_h16; kc = k0; } else { ah = g_v16; kc = k0 - HID; }
        uint32_t dst = sb + buf * 20480;
        #pragma unroll
        for (int it = 0; it < 4; it++) {
            int idx = t + it * 256;
            const __half* gp;
            uint32_t s;
            if (idx < 512) {
                int row = idx >> 2, seg = idx & 3;
                gp = ah + (size_t)(m0 + row) * HID + kc + seg * 8;
                s = dst + row * 80 + seg * 16;
            } else {
                int j = idx - 512, row = j >> 2, seg = j & 3;
                gp = g_Win16 + (size_t)(n0 + row) * KC + k0 + seg * 8;
                s = dst + 10240 + row * 80 + seg * 16;
            }
            CPA16(s, gp);
        }
        CPC();
    };

    const int NS = KC / 32;
    load_stage(0, 0); load_stage(1, 1);
    for (int i = 0; i < NS; i++) {
        if (i + 2 < NS) load_stage(i + 2, (i + 2) & 3); else CPC();
        CPW(2);
        __syncthreads();
        uint32_t As = sb + (i & 3) * 20480, Bs = As + 10240;
        COMPUTE_SP_128x128(As, Bs);
    }

    const int gr = lane >> 2, gc = (lane & 3) * 2;
    #pragma unroll
    for (int mt = 0; mt < 4; mt++)
        #pragma unroll
        for (int half = 0; half < 2; half++) {
            int row = m0 + wm * 64 + mt * 16 + gr + half * 8;
            #pragma unroll
            for (int nt = 0; nt < 4; nt++) {
                int ng = n0 + wn * 32 + nt * 8 + gc;
                float s0 = c[mt][nt][half * 2]     + b_in[ng];
                float s1 = c[mt][nt][half * 2 + 1] + b_in[ng + 1];
                s0 = s0 * sigm(s0); s1 = s1 * sigm(s1);
                *(__half2*)(g_c16 + (size_t)row * CD + ng) = __floats2half2_rn(s0, s1);
            }
        }
}

// ---------------- k2: mu_out = mu + h @ W_mu^T (R10 proven config) ----------
__global__ __launch_bounds__(256, 2) void k2_mma(const float* __restrict__ mu,
                                                 float* __restrict__ mu_out)
{
    extern __shared__ char smem[];
    const int t = threadIdx.x, lane = t & 31, wid = t >> 5;
    const int wm = wid >> 2, wn = wid & 3;
    const int m0 = blockIdx.y * 128, n0 = blockIdx.x * 128;
    uint32_t sb = smem_u32(smem);
    float c[4][4][4] = {};

    auto load_stage = [&](int i, int buf) {
        int k0 = i * 32;
        uint32_t dst = sb + buf * 20480;
        #pragma unroll
        for (int it = 0; it < 4; it++) {
            int idx = t + it * 256;
            const __half* gp;
            uint32_t s;
            if (idx < 512) {
                int row = idx >> 2, seg = idx & 3;
                gp = g_h16 + (size_t)(m0 + row) * HID + k0 + seg * 8;
                s = dst + row * 80 + seg * 16;
            } else {
                int j = idx - 512, row = j >> 2, seg = j & 3;
                gp = g_Wmu16 + (size_t)(n0 + row) * HID + k0 + seg * 8;
                s = dst + 10240 + row * 80 + seg * 16;
            }
            CPA16(s, gp);
        }
        CPC();
    };

    const int NS = HID / 32;
    load_stage(0, 0); load_stage(1, 1);
    for (int i = 0; i < NS; i++) {
        if (i + 2 < NS) load_stage(i + 2, (i + 2) & 3); else CPC();
        CPW(2);
        __syncthreads();
        uint32_t As = sb + (i & 3) * 20480, Bs = As + 10240;
        COMPUTE_SP_128x128(As, Bs);
    }

    const int gr = lane >> 2, gc = (lane & 3) * 2;
    #pragma unroll
    for (int mt = 0; mt < 4; mt++)
        #pragma unroll
        for (int half = 0; half < 2; half++) {
            int row = m0 + wm * 64 + mt * 16 + gr + half * 8;
            #pragma unroll
            for (int nt = 0; nt < 4; nt++) {
                int ng = n0 + wn * 32 + nt * 8 + gc;
                float2 o;
                o.x = c[mt][nt][half * 2]     + mu[ng];
                o.y = c[mt][nt][half * 2 + 1] + mu[ng + 1];
                *(float2*)(mu_out + (size_t)row * HID + ng) = o;
            }
        }
}

// ---------------- k3: 3-gate GEMM (K=256) + SMEM-STAGED coalesced epilogue --
__global__ __launch_bounds__(256, 1) void k3_mma(
    const float* __restrict__ h, const float* __restrict__ v,
    const float* __restrict__ b_out, const float* __restrict__ mu_out,
    float* __restrict__ h_next, float* __restrict__ v_next)
{
    extern __shared__ char smem[];
    const int t = threadIdx.x, lane = t & 31, wid = t >> 5;
    const int wm = wid >> 2, wn = wid & 3;
    const int m0 = blockIdx.y * 128, n0 = blockIdx.x * 64;
    uint32_t sb = smem_u32(smem);
    float c[3][4][2][4] = {};

    auto load_stage = [&](int i, int buf) {
        int k0 = i * 32;
        uint32_t dst = sb + buf * 25600;
        #pragma unroll
        for (int it = 0; it < 5; it++) {
            int idx = t + it * 256;
            const __half* gp;
            uint32_t s;
            if (idx < 512) {
                int row = idx >> 2, seg = idx & 3;
                gp = g_c16 + (size_t)(m0 + row) * CD + k0 + seg * 8;
                s = dst + row * 80 + seg * 16;
            } else {
                int j = idx - 512, row = j >> 2, seg = j & 3;
                int g = row >> 6, rg = row & 63;
                gp = g_Wout16 + (size_t)(g * HID + n0 + rg) * CD + k0 + seg * 8;
                s = dst + 10240 + g * 5120 + rg * 80 + seg * 16;
            }
            CPA16(s, gp);
        }
        CPC();
    };

    const int NS = CD / 32;  // 8
    load_stage(0, 0); load_stage(1, 1);
    for (int i = 0; i < NS; i++) {
        if (i + 2 < NS) load_stage(i + 2, (i + 2) & 3); else CPC();
        CPW(2);
        __syncthreads();
        uint32_t As = sb + (i & 3) * 25600, Bs = As + 10240;
        #pragma unroll
        for (int kk = 0; kk < 32; kk += 16) {
            uint32_t ah[4][4];
            uint32_t aoff = As + wm * 5120 + (lane & 15) * 80 + (lane >> 4) * 16 + kk * 2;
            #pragma unroll
            for (int mt = 0; mt < 4; mt++) ldsm4(ah[mt], aoff + mt * 1280);
            uint32_t boff = Bs + wn * 1280 + ((lane & 7) + ((lane >> 3) & 1) * 8) * 80
                            + (lane >> 4) * 16 + kk * 2;
            #pragma unroll
            for (int g = 0; g < 3; g++) {
                uint32_t bh[4];
                ldsm4(bh, boff + g * 5120);
                #pragma unroll
                for (int mt = 0; mt < 4; mt++) {
                    mma_f16(c[g][mt][0], ah[mt], bh[0], bh[2]);
                    mma_f16(c[g][mt][1], ah[mt], bh[1], bh[3]);
                }
            }
        }
    }

    // ---- stage accumulators into smem (reuse pipeline buffers), then do a
    //      fully coalesced row-major epilogue. S layout: [gate][128][65] fp32.
    __syncthreads();                         // all warps past last ldsm
    float* S = (float*)smem;                 // 3*128*65*4 = 99840 B <= 102400
    const int gr = lane >> 2, gc = (lane & 3) * 2;
    #pragma unroll
    for (int g = 0; g < 3; g++)
        #pragma unroll
        for (int mt = 0; mt < 4; mt++)
            #pragma unroll
            for (int half = 0; half < 2; half++) {
                int r = wm * 64 + mt * 16 + gr + half * 8;
                #pragma unroll
                for (int nt = 0; nt < 2; nt++) {
                    int ccol = wn * 16 + nt * 8 + gc;
                    S[g * 8320 + r * 65 + ccol]     = c[g][mt][nt][half * 2];
                    S[g * 8320 + r * 65 + ccol + 1] = c[g][mt][nt][half * 2 + 1];
                }
            }
    __syncthreads();

    for (int idx = t; idx < 128 * 64; idx += 256) {
        int r = idx >> 6, cc = idx & 63;
        int n = n0 + cc;
        size_t o = (size_t)(m0 + r) * HID + n;
        float a0 = S[r * 65 + cc]            + b_out[n];
        float b0 = S[8320 + r * 65 + cc]     + b_out[HID + n];
        float g0 = S[16640 + r * 65 + cc]    + b_out[2 * HID + n];
        float al = sigm(a0);
        float be = fminf(fmaxf(b0, 0.f) + log1pf(expf(-fabsf(b0))), 2.0f);
        float gt = sigm(g0);
        float hv = h[o], vv = v[o], mc = mu_out[o];
        float vn = al * vv - be * (hv - mc);
        vn = fminf(fmaxf(vn, -10.f), 10.f);
        h_next[o] = hv + 0.1f * gt * vn;
        v_next[o] = vn;
    }
}

// ---------------- launch ----------------
extern "C" void kernel_launch(void* const* d_in, const int* in_sizes, int n_in,
                              void* d_out, int out_size)
{
    const float* h     = (const float*)d_in[0];
    const float* v     = (const float*)d_in[1];
    const float* W_in  = (const float*)d_in[2];
    const float* b_in  = (const float*)d_in[3];
    const float* W_out = (const float*)d_in[4];
    const float* b_out = (const float*)d_in[5];
    const float* W_mu  = (const float*)d_in[6];
    const float* mu    = (const float*)d_in[7];

    float* out    = (float*)d_out;
    float* h_next = out;
    float* v_next = out + (size_t)NB * HID;
    float* mu_out = out + 2 * (size_t)NB * HID;

    cudaFuncSetAttribute(k1_mma, cudaFuncAttributeMaxDynamicSharedMemorySize, 4 * 20480);
    cudaFuncSetAttribute(k2_mma, cudaFuncAttributeMaxDynamicSharedMemorySize, 4 * 20480);
    cudaFuncSetAttribute(k3_mma, cudaFuncAttributeMaxDynamicSharedMemorySize, 4 * 25600);

    k_conv_all<<<4096, 256>>>(h, v, W_mu, W_in, W_out);                  // launch 1

    k1_mma<<<dim3(CD / 128,  NB / 128), 256, 4 * 20480>>>(b_in);         // launch 2
    k2_mma<<<dim3(HID / 128, NB / 128), 256, 4 * 20480>>>(mu, mu_out);   // launch 3
    k3_mma<<<dim3(HID / 64,  NB / 128), 256, 4 * 25600>>>(h, v, b_out,   // launch 4 -> profiled
                                                          mu_out, h_next, v_next);
}